// round 1
// baseline (speedup 1.0000x reference)
#include <cuda_runtime.h>

// Problem constants (fixed by the dataset)
#define NN   100000
#define EE   1600000
#define ET   (EE + NN)       // edges + self loops = 1,700,000
#define C    128
#define DIN  6
#define OUTD 2

// ---------------- device scratch (no allocations allowed) ----------------
__device__ float    g_xl[NN * C];     // x @ Wl + bl
__device__ float    g_xr[NN * C];     // x @ Wr + br
__device__ float    g_h [NN * C];     // GAT accum -> relu'd h
__device__ float    g_t [NN * C];     // GCN scatter accum (pre-GEMM)
__device__ float    g_h2[NN * C];     // relu(t@W2 + b_gcn)
__device__ float    g_logit[ET];
__device__ float    g_ex[ET];         // exp(logit - max) -> alpha
__device__ int      g_src[ET];
__device__ int      g_dst[ET];
__device__ unsigned g_lmax[NN];       // encoded float max
__device__ float    g_den[NN];
__device__ float    g_deg[NN];
__device__ float    g_dinv[NN];

// monotone float <-> uint encoding for atomicMax over floats
__device__ __forceinline__ unsigned fenc(float f) {
    unsigned u = __float_as_uint(f);
    return (u & 0x80000000u) ? ~u : (u | 0x80000000u);
}
__device__ __forceinline__ float fdec(unsigned u) {
    return (u & 0x80000000u) ? __uint_as_float(u & 0x7fffffffu)
                             : __uint_as_float(~u);
}

// ---------------- K0: zero init ----------------
__global__ void k_zero() {
    int idx = blockIdx.x * blockDim.x + threadIdx.x;
    if (idx < NN * C) { g_h[idx] = 0.f; g_t[idx] = 0.f; }
    if (idx < NN)     { g_lmax[idx] = 0u; g_den[idx] = 0.f; g_deg[idx] = 0.f; }
}

// ---------------- K1: xl = x@Wl + bl ; xr = x@Wr + br ----------------
__global__ void k_lin(const float* __restrict__ x,
                      const float* __restrict__ Wl, const float* __restrict__ bl,
                      const float* __restrict__ Wr, const float* __restrict__ br) {
    int idx = blockIdx.x * blockDim.x + threadIdx.x;
    if (idx >= NN * C) return;
    int n = idx >> 7, c = idx & 127;
    float a = bl[c], b = br[c];
#pragma unroll
    for (int k = 0; k < DIN; k++) {
        float xv = x[n * DIN + k];
        a += xv * Wl[k * C + c];
        b += xv * Wr[k * C + c];
    }
    g_xl[idx] = a;
    g_xr[idx] = b;
}

// ---------------- K2: per-edge logits + segment max (warp per edge) ----------------
__global__ void k_logit(const int* __restrict__ ei, const float* __restrict__ ew,
                        const float* __restrict__ We, const float* __restrict__ att,
                        float* __restrict__ out, long long out_size) {
    int w    = (blockIdx.x * blockDim.x + threadIdx.x) >> 5;
    int lane = threadIdx.x & 31;
    if (w >= ET) return;

    int s, d; float e0 = 0.f, e1 = 0.f;
    if (w < EE) {
        s = ei[w]; d = ei[EE + w];
        float2 ev = *(const float2*)&ew[2 * w];
        e0 = ev.x; e1 = ev.y;
    } else {
        s = w - EE; d = s;           // self loop, zero edge feature
    }

    int c = lane * 4;
    float4 a  = *(const float4*)&g_xl[s * C + c];
    float4 b  = *(const float4*)&g_xr[d * C + c];
    float4 w0 = *(const float4*)&We[c];
    float4 w1 = *(const float4*)&We[C + c];
    float4 at = *(const float4*)&att[c];

    float p = 0.f, m;
    m = a.x + b.x + e0 * w0.x + e1 * w1.x; m = m > 0.f ? m : 0.2f * m; p += m * at.x;
    m = a.y + b.y + e0 * w0.y + e1 * w1.y; m = m > 0.f ? m : 0.2f * m; p += m * at.y;
    m = a.z + b.z + e0 * w0.z + e1 * w1.z; m = m > 0.f ? m : 0.2f * m; p += m * at.z;
    m = a.w + b.w + e0 * w0.w + e1 * w1.w; m = m > 0.f ? m : 0.2f * m; p += m * at.w;

#pragma unroll
    for (int o = 16; o; o >>= 1) p += __shfl_xor_sync(0xffffffffu, p, o);

    if (lane == 0) {
        g_logit[w] = p;
        g_src[w] = s;
        g_dst[w] = d;
        atomicMax(&g_lmax[d], fenc(p));
        // output 2: stacked [src; dst] (cast to float)
        if (out_size >= (long long)NN * OUTD + 2LL * ET) {
            out[(long long)NN * OUTD + w]      = (float)s;
            out[(long long)NN * OUTD + ET + w] = (float)d;
        }
    }
}

// ---------------- K3: ex = exp(logit - max[dst]); den[dst] += ex ----------------
__global__ void k_exp() {
    int e = blockIdx.x * blockDim.x + threadIdx.x;
    if (e >= ET) return;
    int d = g_dst[e];
    float ex = __expf(g_logit[e] - fdec(g_lmax[d]));
    g_ex[e] = ex;
    atomicAdd(&g_den[d], ex);
}

// ---------------- K4: alpha; h[dst] += alpha*xl[src]; deg[dst] += alpha ----------------
__global__ void k_alpha(float* __restrict__ out, long long out_size) {
    int w    = (blockIdx.x * blockDim.x + threadIdx.x) >> 5;
    int lane = threadIdx.x & 31;
    if (w >= ET) return;
    int s = g_src[w], d = g_dst[w];
    float alpha = g_ex[w] / g_den[d];

    int c = lane * 4;
    float4 a = *(const float4*)&g_xl[s * C + c];
    float* hp = &g_h[d * C + c];
    atomicAdd(hp + 0, alpha * a.x);
    atomicAdd(hp + 1, alpha * a.y);
    atomicAdd(hp + 2, alpha * a.z);
    atomicAdd(hp + 3, alpha * a.w);

    if (lane == 0) {
        g_ex[w] = alpha;                       // reuse as alpha store
        atomicAdd(&g_deg[d], alpha);
        // output 3: alpha [Et, 1]
        if (out_size >= (long long)NN * OUTD + 3LL * ET)
            out[(long long)NN * OUTD + 2LL * ET + w] = alpha;
    }
}

// ---------------- K5: h = relu(h + b_gat); dinv = deg>0 ? rsqrt(deg) : 0 ----------------
__global__ void k_node(const float* __restrict__ b_gat) {
    int idx = blockIdx.x * blockDim.x + threadIdx.x;
    if (idx < NN * C) {
        float v = g_h[idx] + b_gat[idx & 127];
        g_h[idx] = v > 0.f ? v : 0.f;
    }
    if (idx < NN) {
        float dg = g_deg[idx];
        g_dinv[idx] = dg > 0.f ? rsqrtf(dg) : 0.f;
    }
}

// ---------------- K6: t[dst] += (dinv[src]*alpha*dinv[dst]) * h[src] ----------------
__global__ void k_gcn() {
    int w    = (blockIdx.x * blockDim.x + threadIdx.x) >> 5;
    int lane = threadIdx.x & 31;
    if (w >= ET) return;
    int s = g_src[w], d = g_dst[w];
    float norm = g_dinv[s] * g_ex[w] * g_dinv[d];

    int c = lane * 4;
    float4 hv = *(const float4*)&g_h[s * C + c];
    float* tp = &g_t[d * C + c];
    atomicAdd(tp + 0, norm * hv.x);
    atomicAdd(tp + 1, norm * hv.y);
    atomicAdd(tp + 2, norm * hv.z);
    atomicAdd(tp + 3, norm * hv.w);
}

// ---------------- K7: h2 = relu(t @ W2 + b_gcn)   (smem-tiled GEMM) ----------------
// block: 256 threads, tile 64 rows x 128 cols. ws = W2 (64KB), ts = t tile (32KB).
__global__ void k_gemm(const float* __restrict__ W2, const float* __restrict__ bg) {
    extern __shared__ float sm[];
    float* ws = sm;           // C*C
    float* ts = sm + C * C;   // 64*C

    for (int i = threadIdx.x; i < C * C; i += 256) ws[i] = W2[i];
    int rowBase = blockIdx.x * 64;
    for (int i = threadIdx.x; i < 64 * C; i += 256) {
        int r = rowBase + (i >> 7);
        ts[i] = (r < NN) ? g_t[r * C + (i & 127)] : 0.f;
    }
    __syncthreads();

    int lane = threadIdx.x & 31, warp = threadIdx.x >> 5;
    float acc[8][4] = {};
#pragma unroll 4
    for (int k = 0; k < C; k++) {
        float4 wv = *(const float4*)&ws[k * C + lane * 4];
#pragma unroll
        for (int i = 0; i < 8; i++) {
            float tv = ts[(warp * 8 + i) * C + k];   // warp-uniform broadcast
            acc[i][0] += tv * wv.x;
            acc[i][1] += tv * wv.y;
            acc[i][2] += tv * wv.z;
            acc[i][3] += tv * wv.w;
        }
    }
    float4 bb = *(const float4*)&bg[lane * 4];
#pragma unroll
    for (int i = 0; i < 8; i++) {
        int r = rowBase + warp * 8 + i;
        if (r < NN) {
            float4 v;
            v.x = acc[i][0] + bb.x; v.x = v.x > 0.f ? v.x : 0.f;
            v.y = acc[i][1] + bb.y; v.y = v.y > 0.f ? v.y : 0.f;
            v.z = acc[i][2] + bb.z; v.z = v.z > 0.f ? v.z : 0.f;
            v.w = acc[i][3] + bb.w; v.w = v.w > 0.f ? v.w : 0.f;
            *(float4*)&g_h2[r * C + lane * 4] = v;
        }
    }
}

// ---------------- K8: out = h2 @ W3 + b3   (warp per node) ----------------
__global__ void k_out(const float* __restrict__ W3, const float* __restrict__ b3,
                      float* __restrict__ out) {
    int n    = (blockIdx.x * blockDim.x + threadIdx.x) >> 5;
    int lane = threadIdx.x & 31;
    if (n >= NN) return;
    int c = lane * 4;
    float4 v   = *(const float4*)&g_h2[n * C + c];
    float4 w3a = *(const float4*)&W3[c * 2];       // W3[c..c+1][0..1]
    float4 w3b = *(const float4*)&W3[c * 2 + 4];   // W3[c+2..c+3][0..1]
    float p0 = v.x * w3a.x + v.y * w3a.z + v.z * w3b.x + v.w * w3b.z;
    float p1 = v.x * w3a.y + v.y * w3a.w + v.z * w3b.y + v.w * w3b.w;
#pragma unroll
    for (int o = 16; o; o >>= 1) {
        p0 += __shfl_xor_sync(0xffffffffu, p0, o);
        p1 += __shfl_xor_sync(0xffffffffu, p1, o);
    }
    if (lane == 0) {
        out[n * 2 + 0] = p0 + b3[0];
        out[n * 2 + 1] = p1 + b3[1];
    }
}

// ---------------- launch ----------------
extern "C" void kernel_launch(void* const* d_in, const int* in_sizes, int n_in,
                              void* d_out, int out_size) {
    const float* x    = (const float*)d_in[0];
    const int*   ei   = (const int*)  d_in[1];
    const float* ew   = (const float*)d_in[2];
    const float* Wl   = (const float*)d_in[3];
    const float* bl   = (const float*)d_in[4];
    const float* Wr   = (const float*)d_in[5];
    const float* br   = (const float*)d_in[6];
    const float* We   = (const float*)d_in[7];
    const float* att  = (const float*)d_in[8];
    const float* bgat = (const float*)d_in[9];
    const float* W2   = (const float*)d_in[10];
    const float* bgcn = (const float*)d_in[11];
    const float* W3   = (const float*)d_in[12];
    const float* b3   = (const float*)d_in[13];
    float* out = (float*)d_out;
    long long osz = (long long)out_size;

    static bool attr_set = false;
    if (!attr_set) {
        cudaFuncSetAttribute(k_gemm, cudaFuncAttributeMaxDynamicSharedMemorySize,
                             (C * C + 64 * C) * (int)sizeof(float));
        attr_set = true;
    }

    const int TPB = 256;
    k_zero <<<(NN * C + TPB - 1) / TPB, TPB>>>();
    k_lin  <<<(NN * C + TPB - 1) / TPB, TPB>>>(x, Wl, bl, Wr, br);
    k_logit<<<(ET + 7) / 8, TPB>>>(ei, ew, We, att, out, osz);
    k_exp  <<<(ET + TPB - 1) / TPB, TPB>>>();
    k_alpha<<<(ET + 7) / 8, TPB>>>(out, osz);
    k_node <<<(NN * C + TPB - 1) / TPB, TPB>>>(bgat);
    k_gcn  <<<(ET + 7) / 8, TPB>>>();
    k_gemm <<<(NN + 63) / 64, TPB, (C * C + 64 * C) * sizeof(float)>>>(W2, bgcn);
    k_out  <<<(NN + 7) / 8, TPB>>>(W3, b3, out);
}

// round 2
// speedup vs baseline: 2.0686x; 2.0686x over previous
#include <cuda_runtime.h>

#define NN   100000
#define EE   1600000
#define ET   (EE + NN)     // 1,700,000
#define C    128
#define DIN  6

// ---------------- device scratch ----------------
__device__ float g_xl[NN * C];
__device__ float g_xr[NN * C];
__device__ float g_h [NN * C];
__device__ float g_t [NN * C];
__device__ float g_logit[ET];     // CSR-ordered logits
__device__ float g_alpha[ET];     // CSR-ordered alpha
__device__ uint4 g_csr[ET];       // (src, eid, e0bits, e1bits)
__device__ int   g_cnt[NN];
__device__ int   g_rowptr[NN + 1];
__device__ int   g_cur[NN];

// ---------------- K0: zero histogram ----------------
__global__ void k_zerocnt() {
    int i = blockIdx.x * blockDim.x + threadIdx.x;
    if (i < NN) g_cnt[i] = 0;
}

// ---------------- K1: histogram over dst + write src/dst stack output ----------------
__global__ void k_hist(const int* __restrict__ ei, float* __restrict__ out) {
    int e = blockIdx.x * blockDim.x + threadIdx.x;
    if (e >= ET) return;
    int s, d;
    if (e < EE) { s = ei[e]; d = ei[EE + e]; }
    else        { s = e - EE; d = s; }
    atomicAdd(&g_cnt[d], 1);
    out[NN * 2 + e]      = (float)s;
    out[NN * 2 + ET + e] = (float)d;
}

// ---------------- K2: exclusive scan (single block, 1024 threads) ----------------
__global__ void k_scan() {
    __shared__ int ssum[1024];
    const int CH = (NN + 1023) / 1024;   // 98
    int t = threadIdx.x;
    int beg = t * CH; if (beg > NN) beg = NN;
    int end = beg + CH; if (end > NN) end = NN;
    int s = 0;
    for (int j = beg; j < end; j++) s += g_cnt[j];
    ssum[t] = s;
    __syncthreads();
    // inclusive Hillis-Steele scan
    for (int off = 1; off < 1024; off <<= 1) {
        int v = (t >= off) ? ssum[t - off] : 0;
        __syncthreads();
        ssum[t] += v;
        __syncthreads();
    }
    int run = t ? ssum[t - 1] : 0;
    for (int j = beg; j < end; j++) {
        g_rowptr[j] = run;
        g_cur[j]    = run;
        run += g_cnt[j];
    }
    if (t == 0) g_rowptr[NN] = ET;
}

// ---------------- K3: scatter edges into CSR slots ----------------
__global__ void k_scatter(const int* __restrict__ ei, const float* __restrict__ ew) {
    int e = blockIdx.x * blockDim.x + threadIdx.x;
    if (e >= ET) return;
    int s, d; float e0 = 0.f, e1 = 0.f;
    if (e < EE) {
        s = ei[e]; d = ei[EE + e];
        float2 v = *(const float2*)&ew[2 * e];
        e0 = v.x; e1 = v.y;
    } else { s = e - EE; d = s; }
    int pos = atomicAdd(&g_cur[d], 1);
    g_csr[pos] = make_uint4((unsigned)s, (unsigned)e,
                            __float_as_uint(e0), __float_as_uint(e1));
}

// ---------------- K4: xl = x@Wl + bl ; xr = x@Wr + br ----------------
__global__ void k_lin(const float* __restrict__ x,
                      const float* __restrict__ Wl, const float* __restrict__ bl,
                      const float* __restrict__ Wr, const float* __restrict__ br) {
    int idx = blockIdx.x * blockDim.x + threadIdx.x;
    if (idx >= NN * C) return;
    int n = idx >> 7, c = idx & 127;
    float a = bl[c], b = br[c];
#pragma unroll
    for (int k = 0; k < DIN; k++) {
        float xv = x[n * DIN + k];
        a += xv * Wl[k * C + c];
        b += xv * Wr[k * C + c];
    }
    g_xl[idx] = a;
    g_xr[idx] = b;
}

// ---------------- K5: fused GATv2 per dst node (warp per node, no atomics) ----------------
__global__ void k_gat(const float* __restrict__ We, const float* __restrict__ att,
                      const float* __restrict__ bgat, float* __restrict__ out) {
    int node = (blockIdx.x * blockDim.x + threadIdx.x) >> 5;
    int lane = threadIdx.x & 31;
    if (node >= NN) return;
    int c = lane * 4;
    float4 w0 = *(const float4*)&We[c];
    float4 w1 = *(const float4*)&We[C + c];
    float4 at = *(const float4*)&att[c];
    float4 xr = *(const float4*)&g_xr[node * C + c];
    int beg = g_rowptr[node], end = g_rowptr[node + 1];

    // pass 1: logits + running max
    float mx = -1e30f;
    for (int j = beg; j < end; j++) {
        uint4 pk = g_csr[j];
        float e0 = __uint_as_float(pk.z), e1 = __uint_as_float(pk.w);
        const float4 a = *(const float4*)&g_xl[pk.x * C + c];
        float p = 0.f, m;
        m = a.x + xr.x + e0 * w0.x + e1 * w1.x; m = m > 0.f ? m : 0.2f * m; p += m * at.x;
        m = a.y + xr.y + e0 * w0.y + e1 * w1.y; m = m > 0.f ? m : 0.2f * m; p += m * at.y;
        m = a.z + xr.z + e0 * w0.z + e1 * w1.z; m = m > 0.f ? m : 0.2f * m; p += m * at.z;
        m = a.w + xr.w + e0 * w0.w + e1 * w1.w; m = m > 0.f ? m : 0.2f * m; p += m * at.w;
#pragma unroll
        for (int o = 16; o; o >>= 1) p += __shfl_xor_sync(0xffffffffu, p, o);
        if (lane == 0) g_logit[j] = p;
        mx = fmaxf(mx, p);
    }
    __syncwarp();

    // pass 2: denominator
    float den = 0.f;
    for (int j = beg; j < end; j++) den += __expf(g_logit[j] - mx);
    float inv = 1.f / den;

    // pass 3: alpha + weighted accumulation of xl[src]
    float4 acc = make_float4(0.f, 0.f, 0.f, 0.f);
    for (int j = beg; j < end; j++) {
        uint4 pk = g_csr[j];
        float alpha = __expf(g_logit[j] - mx) * inv;
        const float4 a = *(const float4*)&g_xl[pk.x * C + c];
        acc.x += alpha * a.x;
        acc.y += alpha * a.y;
        acc.z += alpha * a.z;
        acc.w += alpha * a.w;
        if (lane == 0) {
            g_alpha[j] = alpha;
            out[(long long)NN * 2 + 2LL * ET + pk.y] = alpha;   // alpha in original edge order
        }
    }
    float4 bb = *(const float4*)&bgat[c];
    float4 h;
    h.x = fmaxf(acc.x + bb.x, 0.f);
    h.y = fmaxf(acc.y + bb.y, 0.f);
    h.z = fmaxf(acc.z + bb.z, 0.f);
    h.w = fmaxf(acc.w + bb.w, 0.f);
    *(float4*)&g_h[node * C + c] = h;
}

// ---------------- K6: GCN aggregate: t[d] = sum alpha * h[src]   (deg==1 => norm==alpha) ----------------
__global__ void k_gcn() {
    int node = (blockIdx.x * blockDim.x + threadIdx.x) >> 5;
    int lane = threadIdx.x & 31;
    if (node >= NN) return;
    int c = lane * 4;
    int beg = g_rowptr[node], end = g_rowptr[node + 1];
    float4 acc = make_float4(0.f, 0.f, 0.f, 0.f);
    for (int j = beg; j < end; j++) {
        int s = g_csr[j].x;
        float alpha = g_alpha[j];
        const float4 hv = *(const float4*)&g_h[s * C + c];
        acc.x += alpha * hv.x;
        acc.y += alpha * hv.y;
        acc.z += alpha * hv.z;
        acc.w += alpha * hv.w;
    }
    *(float4*)&g_t[node * C + c] = acc;
}

// ---------------- K7: out = relu(t@W2 + b_gcn) @ W3 + b3  (fused GEMM + head) ----------------
__global__ void k_gemm(const float* __restrict__ W2, const float* __restrict__ bg,
                       const float* __restrict__ W3, const float* __restrict__ b3,
                       float* __restrict__ out) {
    extern __shared__ float sm[];
    float* ws = sm;           // C*C
    float* ts = sm + C * C;   // 64*C

    for (int i = threadIdx.x; i < C * C; i += 256) ws[i] = W2[i];
    int rowBase = blockIdx.x * 64;
    for (int i = threadIdx.x; i < 64 * C; i += 256) {
        int r = rowBase + (i >> 7);
        ts[i] = (r < NN) ? g_t[r * C + (i & 127)] : 0.f;
    }
    __syncthreads();

    int lane = threadIdx.x & 31, warp = threadIdx.x >> 5;
    float acc[8][4] = {};
#pragma unroll 4
    for (int k = 0; k < C; k++) {
        float4 wv = *(const float4*)&ws[k * C + lane * 4];
#pragma unroll
        for (int i = 0; i < 8; i++) {
            float tv = ts[(warp * 8 + i) * C + k];
            acc[i][0] += tv * wv.x;
            acc[i][1] += tv * wv.y;
            acc[i][2] += tv * wv.z;
            acc[i][3] += tv * wv.w;
        }
    }
    int c = lane * 4;
    float4 bb  = *(const float4*)&bg[c];
    float4 w3a = *(const float4*)&W3[c * 2];       // (W3[c][0],W3[c][1],W3[c+1][0],W3[c+1][1])
    float4 w3b = *(const float4*)&W3[c * 2 + 4];
    float b30 = b3[0], b31 = b3[1];
#pragma unroll
    for (int i = 0; i < 8; i++) {
        float4 v;
        v.x = fmaxf(acc[i][0] + bb.x, 0.f);
        v.y = fmaxf(acc[i][1] + bb.y, 0.f);
        v.z = fmaxf(acc[i][2] + bb.z, 0.f);
        v.w = fmaxf(acc[i][3] + bb.w, 0.f);
        float p0 = v.x * w3a.x + v.y * w3a.z + v.z * w3b.x + v.w * w3b.z;
        float p1 = v.x * w3a.y + v.y * w3a.w + v.z * w3b.y + v.w * w3b.w;
#pragma unroll
        for (int o = 16; o; o >>= 1) {
            p0 += __shfl_xor_sync(0xffffffffu, p0, o);
            p1 += __shfl_xor_sync(0xffffffffu, p1, o);
        }
        int r = rowBase + warp * 8 + i;
        if (lane == 0 && r < NN) {
            out[r * 2 + 0] = p0 + b30;
            out[r * 2 + 1] = p1 + b31;
        }
    }
}

// ---------------- launch ----------------
extern "C" void kernel_launch(void* const* d_in, const int* in_sizes, int n_in,
                              void* d_out, int out_size) {
    const float* x    = (const float*)d_in[0];
    const int*   ei   = (const int*)  d_in[1];
    const float* ew   = (const float*)d_in[2];
    const float* Wl   = (const float*)d_in[3];
    const float* bl   = (const float*)d_in[4];
    const float* Wr   = (const float*)d_in[5];
    const float* br   = (const float*)d_in[6];
    const float* We   = (const float*)d_in[7];
    const float* att  = (const float*)d_in[8];
    const float* bgat = (const float*)d_in[9];
    const float* W2   = (const float*)d_in[10];
    const float* bgcn = (const float*)d_in[11];
    const float* W3   = (const float*)d_in[12];
    const float* b3   = (const float*)d_in[13];
    float* out = (float*)d_out;

    static bool attr_set = false;
    if (!attr_set) {
        cudaFuncSetAttribute(k_gemm, cudaFuncAttributeMaxDynamicSharedMemorySize,
                             (C * C + 64 * C) * (int)sizeof(float));
        attr_set = true;
    }

    const int TPB = 256;
    k_zerocnt<<<(NN + TPB - 1) / TPB, TPB>>>();
    k_hist   <<<(ET + TPB - 1) / TPB, TPB>>>(ei, out);
    k_scan   <<<1, 1024>>>();
    k_scatter<<<(ET + TPB - 1) / TPB, TPB>>>(ei, ew);
    k_lin    <<<(NN * C + TPB - 1) / TPB, TPB>>>(x, Wl, bl, Wr, br);
    k_gat    <<<(NN * 32 + TPB - 1) / TPB, TPB>>>(We, att, bgat, out);
    k_gcn    <<<(NN * 32 + TPB - 1) / TPB, TPB>>>();
    k_gemm   <<<(NN + 63) / 64, TPB, (C * C + 64 * C) * sizeof(float)>>>(W2, bgcn, W3, b3, out);
}

// round 3
// speedup vs baseline: 2.2249x; 1.0755x over previous
#include <cuda_runtime.h>

#define NN   100000
#define EE   1600000
#define ET   (EE + NN)     // 1,700,000
#define C    128
#define DIN  6

// ---------------- device scratch ----------------
__device__ float g_xl[NN * C];
__device__ float g_xr[NN * C];
__device__ float g_h [NN * C];
__device__ float g_t [NN * C];
__device__ float g_logit[ET];     // CSR-ordered logits
__device__ float g_alpha[ET];     // CSR-ordered alpha
__device__ uint4 g_csr[ET];       // (src, eid, e0bits, e1bits)
__device__ int   g_cnt[NN];
__device__ int   g_rowptr[NN + 1];
__device__ int   g_cur[NN];

// ---------------- K0: zero histogram ----------------
__global__ void k_zerocnt() {
    int i = blockIdx.x * blockDim.x + threadIdx.x;
    if (i < NN) g_cnt[i] = 0;
}

// ---------------- K1: histogram over dst + write src/dst stack output ----------------
__global__ void k_hist(const int* __restrict__ ei, float* __restrict__ out) {
    int e = blockIdx.x * blockDim.x + threadIdx.x;
    if (e >= ET) return;
    int s, d;
    if (e < EE) { s = ei[e]; d = ei[EE + e]; }
    else        { s = e - EE; d = s; }
    atomicAdd(&g_cnt[d], 1);
    out[NN * 2 + e]      = (float)s;
    out[NN * 2 + ET + e] = (float)d;
}

// ---------------- K2: exclusive scan (single block, 1024 threads) ----------------
__global__ void k_scan() {
    __shared__ int ssum[1024];
    const int CH = (NN + 1023) / 1024;   // 98
    int t = threadIdx.x;
    int beg = t * CH; if (beg > NN) beg = NN;
    int end = beg + CH; if (end > NN) end = NN;
    int s = 0;
    for (int j = beg; j < end; j++) s += g_cnt[j];
    ssum[t] = s;
    __syncthreads();
    for (int off = 1; off < 1024; off <<= 1) {
        int v = (t >= off) ? ssum[t - off] : 0;
        __syncthreads();
        ssum[t] += v;
        __syncthreads();
    }
    int run = t ? ssum[t - 1] : 0;
    for (int j = beg; j < end; j++) {
        g_rowptr[j] = run;
        g_cur[j]    = run;
        run += g_cnt[j];
    }
    if (t == 0) g_rowptr[NN] = ET;
}

// ---------------- K3: scatter edges into CSR slots ----------------
__global__ void k_scatter(const int* __restrict__ ei, const float* __restrict__ ew) {
    int e = blockIdx.x * blockDim.x + threadIdx.x;
    if (e >= ET) return;
    int s, d; float e0 = 0.f, e1 = 0.f;
    if (e < EE) {
        s = ei[e]; d = ei[EE + e];
        float2 v = *(const float2*)&ew[2 * e];
        e0 = v.x; e1 = v.y;
    } else { s = e - EE; d = s; }
    int pos = atomicAdd(&g_cur[d], 1);
    g_csr[pos] = make_uint4((unsigned)s, (unsigned)e,
                            __float_as_uint(e0), __float_as_uint(e1));
}

// ---------------- K4: xl = x@Wl + bl ; xr = x@Wr + br ----------------
__global__ void k_lin(const float* __restrict__ x,
                      const float* __restrict__ Wl, const float* __restrict__ bl,
                      const float* __restrict__ Wr, const float* __restrict__ br) {
    int idx = blockIdx.x * blockDim.x + threadIdx.x;
    if (idx >= NN * C) return;
    int n = idx >> 7, c = idx & 127;
    float a = bl[c], b = br[c];
#pragma unroll
    for (int k = 0; k < DIN; k++) {
        float xv = x[n * DIN + k];
        a += xv * Wl[k * C + c];
        b += xv * Wr[k * C + c];
    }
    g_xl[idx] = a;
    g_xr[idx] = b;
}

// helper: compute edge logit contribution for this lane's 4 channels + full warp reduce
__device__ __forceinline__ float edge_logit(const uint4 pk, const float4 xr,
                                            const float4 w0, const float4 w1,
                                            const float4 at, int c) {
    float e0 = __uint_as_float(pk.z), e1 = __uint_as_float(pk.w);
    const float4 a = *(const float4*)&g_xl[pk.x * C + c];
    float p = 0.f, m;
    m = a.x + xr.x + e0 * w0.x + e1 * w1.x; m = m > 0.f ? m : 0.2f * m; p += m * at.x;
    m = a.y + xr.y + e0 * w0.y + e1 * w1.y; m = m > 0.f ? m : 0.2f * m; p += m * at.y;
    m = a.z + xr.z + e0 * w0.z + e1 * w1.z; m = m > 0.f ? m : 0.2f * m; p += m * at.z;
    m = a.w + xr.w + e0 * w0.w + e1 * w1.w; m = m > 0.f ? m : 0.2f * m; p += m * at.w;
    return p;
}

// ---------------- K5: fused GATv2, single gather pass (online softmax) ----------------
__global__ void k_gat(const float* __restrict__ We, const float* __restrict__ att,
                      const float* __restrict__ bgat, float* __restrict__ out) {
    int node = (blockIdx.x * blockDim.x + threadIdx.x) >> 5;
    int lane = threadIdx.x & 31;
    if (node >= NN) return;
    int c = lane * 4;
    float4 w0 = *(const float4*)&We[c];
    float4 w1 = *(const float4*)&We[C + c];
    float4 at = *(const float4*)&att[c];
    float4 xr = *(const float4*)&g_xr[node * C + c];
    int beg = g_rowptr[node], end = g_rowptr[node + 1];

    // single pass: online softmax with rescaled accumulator
    float mx = -1e30f, den = 0.f;
    float4 acc = make_float4(0.f, 0.f, 0.f, 0.f);
    int j = beg;
    for (; j + 1 < end; j += 2) {
        uint4 pk0 = g_csr[j];
        uint4 pk1 = g_csr[j + 1];
        const float4 a0 = *(const float4*)&g_xl[pk0.x * C + c];
        const float4 a1 = *(const float4*)&g_xl[pk1.x * C + c];
        float e00 = __uint_as_float(pk0.z), e01 = __uint_as_float(pk0.w);
        float e10 = __uint_as_float(pk1.z), e11 = __uint_as_float(pk1.w);
        float p0 = 0.f, p1 = 0.f, m;
        m = a0.x + xr.x + e00 * w0.x + e01 * w1.x; m = m > 0.f ? m : 0.2f * m; p0 += m * at.x;
        m = a1.x + xr.x + e10 * w0.x + e11 * w1.x; m = m > 0.f ? m : 0.2f * m; p1 += m * at.x;
        m = a0.y + xr.y + e00 * w0.y + e01 * w1.y; m = m > 0.f ? m : 0.2f * m; p0 += m * at.y;
        m = a1.y + xr.y + e10 * w0.y + e11 * w1.y; m = m > 0.f ? m : 0.2f * m; p1 += m * at.y;
        m = a0.z + xr.z + e00 * w0.z + e01 * w1.z; m = m > 0.f ? m : 0.2f * m; p0 += m * at.z;
        m = a1.z + xr.z + e10 * w0.z + e11 * w1.z; m = m > 0.f ? m : 0.2f * m; p1 += m * at.z;
        m = a0.w + xr.w + e00 * w0.w + e01 * w1.w; m = m > 0.f ? m : 0.2f * m; p0 += m * at.w;
        m = a1.w + xr.w + e10 * w0.w + e11 * w1.w; m = m > 0.f ? m : 0.2f * m; p1 += m * at.w;
#pragma unroll
        for (int o = 16; o; o >>= 1) {
            p0 += __shfl_xor_sync(0xffffffffu, p0, o);
            p1 += __shfl_xor_sync(0xffffffffu, p1, o);
        }
        if (lane == 0) { g_logit[j] = p0; g_logit[j + 1] = p1; }
        float pm = fmaxf(mx, fmaxf(p0, p1));
        float scale = __expf(mx - pm);
        float v0 = __expf(p0 - pm);
        float v1 = __expf(p1 - pm);
        den = den * scale + v0 + v1;
        acc.x = acc.x * scale + v0 * a0.x + v1 * a1.x;
        acc.y = acc.y * scale + v0 * a0.y + v1 * a1.y;
        acc.z = acc.z * scale + v0 * a0.z + v1 * a1.z;
        acc.w = acc.w * scale + v0 * a0.w + v1 * a1.w;
        mx = pm;
    }
    if (j < end) {
        uint4 pk = g_csr[j];
        const float4 a = *(const float4*)&g_xl[pk.x * C + c];
        float p = edge_logit(pk, xr, w0, w1, at, c);
#pragma unroll
        for (int o = 16; o; o >>= 1) p += __shfl_xor_sync(0xffffffffu, p, o);
        if (lane == 0) g_logit[j] = p;
        float pm = fmaxf(mx, p);
        float scale = __expf(mx - pm);
        float v = __expf(p - pm);
        den = den * scale + v;
        acc.x = acc.x * scale + v * a.x;
        acc.y = acc.y * scale + v * a.y;
        acc.z = acc.z * scale + v * a.z;
        acc.w = acc.w * scale + v * a.w;
        mx = pm;
    }
    float inv = 1.f / den;

    // pass B: alpha write-out, lanes parallel over edges (cheap: no feature gathers)
    for (int jj = beg + lane; jj < end; jj += 32) {
        float al = __expf(g_logit[jj] - mx) * inv;
        g_alpha[jj] = al;
        unsigned eid = g_csr[jj].y;
        out[(long long)NN * 2 + 2LL * ET + eid] = al;
    }

    float4 bb = *(const float4*)&bgat[c];
    float4 h;
    h.x = fmaxf(acc.x * inv + bb.x, 0.f);
    h.y = fmaxf(acc.y * inv + bb.y, 0.f);
    h.z = fmaxf(acc.z * inv + bb.z, 0.f);
    h.w = fmaxf(acc.w * inv + bb.w, 0.f);
    *(float4*)&g_h[node * C + c] = h;
}

// ---------------- K6: GCN aggregate: t[d] = sum alpha * h[src]  (deg==1 => norm==alpha) ----------------
__global__ void k_gcn() {
    int node = (blockIdx.x * blockDim.x + threadIdx.x) >> 5;
    int lane = threadIdx.x & 31;
    if (node >= NN) return;
    int c = lane * 4;
    int beg = g_rowptr[node], end = g_rowptr[node + 1];
    float4 acc0 = make_float4(0.f, 0.f, 0.f, 0.f);
    float4 acc1 = make_float4(0.f, 0.f, 0.f, 0.f);
    int j = beg;
    for (; j + 1 < end; j += 2) {
        int s0 = g_csr[j].x, s1 = g_csr[j + 1].x;
        float al0 = g_alpha[j], al1 = g_alpha[j + 1];
        const float4 h0 = *(const float4*)&g_h[s0 * C + c];
        const float4 h1 = *(const float4*)&g_h[s1 * C + c];
        acc0.x += al0 * h0.x; acc1.x += al1 * h1.x;
        acc0.y += al0 * h0.y; acc1.y += al1 * h1.y;
        acc0.z += al0 * h0.z; acc1.z += al1 * h1.z;
        acc0.w += al0 * h0.w; acc1.w += al1 * h1.w;
    }
    if (j < end) {
        int s = g_csr[j].x;
        float al = g_alpha[j];
        const float4 hv = *(const float4*)&g_h[s * C + c];
        acc0.x += al * hv.x;
        acc0.y += al * hv.y;
        acc0.z += al * hv.z;
        acc0.w += al * hv.w;
    }
    acc0.x += acc1.x; acc0.y += acc1.y; acc0.z += acc1.z; acc0.w += acc1.w;
    *(float4*)&g_t[node * C + c] = acc0;
}

// ---------------- K7: out = relu(t@W2 + b_gcn) @ W3 + b3  (fused GEMM + head) ----------------
__global__ void k_gemm(const float* __restrict__ W2, const float* __restrict__ bg,
                       const float* __restrict__ W3, const float* __restrict__ b3,
                       float* __restrict__ out) {
    extern __shared__ float sm[];
    float* ws = sm;           // C*C
    float* ts = sm + C * C;   // 64*C

    for (int i = threadIdx.x; i < C * C; i += 256) ws[i] = W2[i];
    int rowBase = blockIdx.x * 64;
    for (int i = threadIdx.x; i < 64 * C; i += 256) {
        int r = rowBase + (i >> 7);
        ts[i] = (r < NN) ? g_t[r * C + (i & 127)] : 0.f;
    }
    __syncthreads();

    int lane = threadIdx.x & 31, warp = threadIdx.x >> 5;
    float acc[8][4] = {};
#pragma unroll 4
    for (int k = 0; k < C; k++) {
        float4 wv = *(const float4*)&ws[k * C + lane * 4];
#pragma unroll
        for (int i = 0; i < 8; i++) {
            float tv = ts[(warp * 8 + i) * C + k];
            acc[i][0] += tv * wv.x;
            acc[i][1] += tv * wv.y;
            acc[i][2] += tv * wv.z;
            acc[i][3] += tv * wv.w;
        }
    }
    int c = lane * 4;
    float4 bb  = *(const float4*)&bg[c];
    float4 w3a = *(const float4*)&W3[c * 2];
    float4 w3b = *(const float4*)&W3[c * 2 + 4];
    float b30 = b3[0], b31 = b3[1];
#pragma unroll
    for (int i = 0; i < 8; i++) {
        float4 v;
        v.x = fmaxf(acc[i][0] + bb.x, 0.f);
        v.y = fmaxf(acc[i][1] + bb.y, 0.f);
        v.z = fmaxf(acc[i][2] + bb.z, 0.f);
        v.w = fmaxf(acc[i][3] + bb.w, 0.f);
        float p0 = v.x * w3a.x + v.y * w3a.z + v.z * w3b.x + v.w * w3b.z;
        float p1 = v.x * w3a.y + v.y * w3a.w + v.z * w3b.y + v.w * w3b.w;
#pragma unroll
        for (int o = 16; o; o >>= 1) {
            p0 += __shfl_xor_sync(0xffffffffu, p0, o);
            p1 += __shfl_xor_sync(0xffffffffu, p1, o);
        }
        int r = rowBase + warp * 8 + i;
        if (lane == 0 && r < NN) {
            out[r * 2 + 0] = p0 + b30;
            out[r * 2 + 1] = p1 + b31;
        }
    }
}

// ---------------- launch ----------------
extern "C" void kernel_launch(void* const* d_in, const int* in_sizes, int n_in,
                              void* d_out, int out_size) {
    const float* x    = (const float*)d_in[0];
    const int*   ei   = (const int*)  d_in[1];
    const float* ew   = (const float*)d_in[2];
    const float* Wl   = (const float*)d_in[3];
    const float* bl   = (const float*)d_in[4];
    const float* Wr   = (const float*)d_in[5];
    const float* br   = (const float*)d_in[6];
    const float* We   = (const float*)d_in[7];
    const float* att  = (const float*)d_in[8];
    const float* bgat = (const float*)d_in[9];
    const float* W2   = (const float*)d_in[10];
    const float* bgcn = (const float*)d_in[11];
    const float* W3   = (const float*)d_in[12];
    const float* b3   = (const float*)d_in[13];
    float* out = (float*)d_out;

    static bool attr_set = false;
    if (!attr_set) {
        cudaFuncSetAttribute(k_gemm, cudaFuncAttributeMaxDynamicSharedMemorySize,
                             (C * C + 64 * C) * (int)sizeof(float));
        attr_set = true;
    }

    const int TPB = 256;
    k_zerocnt<<<(NN + TPB - 1) / TPB, TPB>>>();
    k_hist   <<<(ET + TPB - 1) / TPB, TPB>>>(ei, out);
    k_scan   <<<1, 1024>>>();
    k_scatter<<<(ET + TPB - 1) / TPB, TPB>>>(ei, ew);
    k_lin    <<<(NN * C + TPB - 1) / TPB, TPB>>>(x, Wl, bl, Wr, br);
    k_gat    <<<(NN * 32 + TPB - 1) / TPB, TPB>>>(We, att, bgat, out);
    k_gcn    <<<(NN * 32 + TPB - 1) / TPB, TPB>>>();
    k_gemm   <<<(NN + 63) / 64, TPB, (C * C + 64 * C) * sizeof(float)>>>(W2, bgcn, W3, b3, out);
}

// round 4
// speedup vs baseline: 2.3705x; 1.0654x over previous
#include <cuda_runtime.h>

#define NN   100000
#define EE   1600000
#define ET   (EE + NN)     // 1,700,000
#define C    128
#define DIN  6

// ---------------- device scratch ----------------
__device__ float  g_xl[NN * C];
__device__ float  g_xr[NN * C];
__device__ float  g_h [NN * C];
__device__ float  g_t [NN * C];
__device__ float  g_ex[ET];        // CSR-ordered exp(logit)
__device__ float  g_alpha[ET];     // CSR-ordered alpha
__device__ int    g_srca[ET];      // CSR-ordered src
__device__ int    g_eid[ET];       // CSR-ordered original edge id
__device__ float2 g_ef[ET];        // CSR-ordered edge features
__device__ int    g_cnt[NN];
__device__ int    g_rowptr[NN + 1];
__device__ int    g_cur[NN];

// ---------------- K0: zero histogram ----------------
__global__ void k_zerocnt() {
    int i = blockIdx.x * blockDim.x + threadIdx.x;
    if (i < NN) g_cnt[i] = 0;
}

// ---------------- K1: histogram over dst + write src/dst stack output ----------------
__global__ void k_hist(const int* __restrict__ ei, float* __restrict__ out) {
    int e = blockIdx.x * blockDim.x + threadIdx.x;
    if (e >= ET) return;
    int s, d;
    if (e < EE) { s = ei[e]; d = ei[EE + e]; }
    else        { s = e - EE; d = s; }
    atomicAdd(&g_cnt[d], 1);
    out[NN * 2 + e]      = (float)s;
    out[NN * 2 + ET + e] = (float)d;
}

// ---------------- K2: exclusive scan (single block, 1024 threads) ----------------
__global__ void k_scan() {
    __shared__ int ssum[1024];
    const int CH = (NN + 1023) / 1024;   // 98
    int t = threadIdx.x;
    int beg = t * CH; if (beg > NN) beg = NN;
    int end = beg + CH; if (end > NN) end = NN;
    int s = 0;
    for (int j = beg; j < end; j++) s += g_cnt[j];
    ssum[t] = s;
    __syncthreads();
    for (int off = 1; off < 1024; off <<= 1) {
        int v = (t >= off) ? ssum[t - off] : 0;
        __syncthreads();
        ssum[t] += v;
        __syncthreads();
    }
    int run = t ? ssum[t - 1] : 0;
    for (int j = beg; j < end; j++) {
        g_rowptr[j] = run;
        g_cur[j]    = run;
        run += g_cnt[j];
    }
    if (t == 0) g_rowptr[NN] = ET;
}

// ---------------- K3: scatter edges into CSR slots ----------------
__global__ void k_scatter(const int* __restrict__ ei, const float* __restrict__ ew) {
    int e = blockIdx.x * blockDim.x + threadIdx.x;
    if (e >= ET) return;
    int s, d; float e0 = 0.f, e1 = 0.f;
    if (e < EE) {
        s = ei[e]; d = ei[EE + e];
        float2 v = *(const float2*)&ew[2 * e];
        e0 = v.x; e1 = v.y;
    } else { s = e - EE; d = s; }
    int pos = atomicAdd(&g_cur[d], 1);
    g_srca[pos] = s;
    g_eid[pos]  = e;
    g_ef[pos]   = make_float2(e0, e1);
}

// ---------------- K4: xl = x@Wl + bl ; xr = x@Wr + br ----------------
__global__ void k_lin(const float* __restrict__ x,
                      const float* __restrict__ Wl, const float* __restrict__ bl,
                      const float* __restrict__ Wr, const float* __restrict__ br) {
    int idx = blockIdx.x * blockDim.x + threadIdx.x;
    if (idx >= NN * C) return;
    int n = idx >> 7, c = idx & 127;
    float a = bl[c], b = br[c];
#pragma unroll
    for (int k = 0; k < DIN; k++) {
        float xv = x[n * DIN + k];
        a += xv * Wl[k * C + c];
        b += xv * Wr[k * C + c];
    }
    g_xl[idx] = a;
    g_xr[idx] = b;
}

// per-lane partial logit for one edge (4 channels)
__device__ __forceinline__ float lane_logit(const float4 a, const float4 xr,
                                            const float2 ef,
                                            const float4 w0, const float4 w1,
                                            const float4 at) {
    float p = 0.f, m;
    m = a.x + xr.x + ef.x * w0.x + ef.y * w1.x; m = m > 0.f ? m : 0.2f * m; p += m * at.x;
    m = a.y + xr.y + ef.x * w0.y + ef.y * w1.y; m = m > 0.f ? m : 0.2f * m; p += m * at.y;
    m = a.z + xr.z + ef.x * w0.z + ef.y * w1.z; m = m > 0.f ? m : 0.2f * m; p += m * at.z;
    m = a.w + xr.w + ef.x * w0.w + ef.y * w1.w; m = m > 0.f ? m : 0.2f * m; p += m * at.w;
    return p;
}

// ---------------- K5: fused GATv2, single gather pass, no max (logits bounded) ----------------
__global__ void k_gat(const float* __restrict__ We, const float* __restrict__ att,
                      const float* __restrict__ bgat, float* __restrict__ out) {
    int node = (blockIdx.x * blockDim.x + threadIdx.x) >> 5;
    int lane = threadIdx.x & 31;
    if (node >= NN) return;
    int c = lane * 4;
    float4 w0 = *(const float4*)&We[c];
    float4 w1 = *(const float4*)&We[C + c];
    float4 at = *(const float4*)&att[c];
    float4 xr = *(const float4*)&g_xr[node * C + c];
    int beg = g_rowptr[node], end = g_rowptr[node + 1];

    float den = 0.f;
    float4 acc = make_float4(0.f, 0.f, 0.f, 0.f);
    int j = beg;
    for (; j + 3 < end; j += 4) {
        int s0 = g_srca[j], s1 = g_srca[j + 1], s2 = g_srca[j + 2], s3 = g_srca[j + 3];
        float2 f0 = g_ef[j], f1 = g_ef[j + 1], f2 = g_ef[j + 2], f3 = g_ef[j + 3];
        const float4 a0 = *(const float4*)&g_xl[s0 * C + c];
        const float4 a1 = *(const float4*)&g_xl[s1 * C + c];
        const float4 a2 = *(const float4*)&g_xl[s2 * C + c];
        const float4 a3 = *(const float4*)&g_xl[s3 * C + c];
        float p0 = lane_logit(a0, xr, f0, w0, w1, at);
        float p1 = lane_logit(a1, xr, f1, w0, w1, at);
        float p2 = lane_logit(a2, xr, f2, w0, w1, at);
        float p3 = lane_logit(a3, xr, f3, w0, w1, at);
#pragma unroll
        for (int o = 16; o; o >>= 1) {
            p0 += __shfl_xor_sync(0xffffffffu, p0, o);
            p1 += __shfl_xor_sync(0xffffffffu, p1, o);
            p2 += __shfl_xor_sync(0xffffffffu, p2, o);
            p3 += __shfl_xor_sync(0xffffffffu, p3, o);
        }
        float v0 = __expf(p0), v1 = __expf(p1), v2 = __expf(p2), v3 = __expf(p3);
        if (lane == 0) {
            g_ex[j] = v0; g_ex[j + 1] = v1; g_ex[j + 2] = v2; g_ex[j + 3] = v3;
        }
        den += (v0 + v1) + (v2 + v3);
        acc.x += v0 * a0.x + v1 * a1.x + v2 * a2.x + v3 * a3.x;
        acc.y += v0 * a0.y + v1 * a1.y + v2 * a2.y + v3 * a3.y;
        acc.z += v0 * a0.z + v1 * a1.z + v2 * a2.z + v3 * a3.z;
        acc.w += v0 * a0.w + v1 * a1.w + v2 * a2.w + v3 * a3.w;
    }
    for (; j < end; j++) {
        int s = g_srca[j];
        float2 f = g_ef[j];
        const float4 a = *(const float4*)&g_xl[s * C + c];
        float p = lane_logit(a, xr, f, w0, w1, at);
#pragma unroll
        for (int o = 16; o; o >>= 1) p += __shfl_xor_sync(0xffffffffu, p, o);
        float v = __expf(p);
        if (lane == 0) g_ex[j] = v;
        den += v;
        acc.x += v * a.x;
        acc.y += v * a.y;
        acc.z += v * a.z;
        acc.w += v * a.w;
    }
    float inv = 1.f / den;

    // pass B: alpha write-out, lanes parallel over edges
    for (int jj = beg + lane; jj < end; jj += 32) {
        float al = g_ex[jj] * inv;
        g_alpha[jj] = al;
        out[(long long)NN * 2 + 2LL * ET + g_eid[jj]] = al;
    }

    float4 bb = *(const float4*)&bgat[c];
    float4 h;
    h.x = fmaxf(acc.x * inv + bb.x, 0.f);
    h.y = fmaxf(acc.y * inv + bb.y, 0.f);
    h.z = fmaxf(acc.z * inv + bb.z, 0.f);
    h.w = fmaxf(acc.w * inv + bb.w, 0.f);
    *(float4*)&g_h[node * C + c] = h;
}

// ---------------- K6: GCN aggregate: t[d] = sum alpha * h[src]  (deg==1 => norm==alpha) ----------------
__global__ void k_gcn() {
    int node = (blockIdx.x * blockDim.x + threadIdx.x) >> 5;
    int lane = threadIdx.x & 31;
    if (node >= NN) return;
    int c = lane * 4;
    int beg = g_rowptr[node], end = g_rowptr[node + 1];
    float4 acc0 = make_float4(0.f, 0.f, 0.f, 0.f);
    float4 acc1 = make_float4(0.f, 0.f, 0.f, 0.f);
    int j = beg;
    for (; j + 3 < end; j += 4) {
        int s0 = g_srca[j], s1 = g_srca[j + 1], s2 = g_srca[j + 2], s3 = g_srca[j + 3];
        float al0 = g_alpha[j], al1 = g_alpha[j + 1], al2 = g_alpha[j + 2], al3 = g_alpha[j + 3];
        const float4 h0 = *(const float4*)&g_h[s0 * C + c];
        const float4 h1 = *(const float4*)&g_h[s1 * C + c];
        const float4 h2 = *(const float4*)&g_h[s2 * C + c];
        const float4 h3 = *(const float4*)&g_h[s3 * C + c];
        acc0.x += al0 * h0.x + al2 * h2.x; acc1.x += al1 * h1.x + al3 * h3.x;
        acc0.y += al0 * h0.y + al2 * h2.y; acc1.y += al1 * h1.y + al3 * h3.y;
        acc0.z += al0 * h0.z + al2 * h2.z; acc1.z += al1 * h1.z + al3 * h3.z;
        acc0.w += al0 * h0.w + al2 * h2.w; acc1.w += al1 * h1.w + al3 * h3.w;
    }
    for (; j < end; j++) {
        int s = g_srca[j];
        float al = g_alpha[j];
        const float4 hv = *(const float4*)&g_h[s * C + c];
        acc0.x += al * hv.x;
        acc0.y += al * hv.y;
        acc0.z += al * hv.z;
        acc0.w += al * hv.w;
    }
    acc0.x += acc1.x; acc0.y += acc1.y; acc0.z += acc1.z; acc0.w += acc1.w;
    *(float4*)&g_t[node * C + c] = acc0;
}

// ---------------- K7: out = relu(t@W2 + b_gcn) @ W3 + b3  (fused GEMM + head) ----------------
__global__ void k_gemm(const float* __restrict__ W2, const float* __restrict__ bg,
                       const float* __restrict__ W3, const float* __restrict__ b3,
                       float* __restrict__ out) {
    extern __shared__ float sm[];
    float* ws = sm;           // C*C
    float* ts = sm + C * C;   // 64*C

    for (int i = threadIdx.x; i < C * C; i += 256) ws[i] = W2[i];
    int rowBase = blockIdx.x * 64;
    for (int i = threadIdx.x; i < 64 * C; i += 256) {
        int r = rowBase + (i >> 7);
        ts[i] = (r < NN) ? g_t[r * C + (i & 127)] : 0.f;
    }
    __syncthreads();

    int lane = threadIdx.x & 31, warp = threadIdx.x >> 5;
    float acc[8][4] = {};
#pragma unroll 4
    for (int k = 0; k < C; k++) {
        float4 wv = *(const float4*)&ws[k * C + lane * 4];
#pragma unroll
        for (int i = 0; i < 8; i++) {
            float tv = ts[(warp * 8 + i) * C + k];
            acc[i][0] += tv * wv.x;
            acc[i][1] += tv * wv.y;
            acc[i][2] += tv * wv.z;
            acc[i][3] += tv * wv.w;
        }
    }
    int c = lane * 4;
    float4 bb  = *(const float4*)&bg[c];
    float4 w3a = *(const float4*)&W3[c * 2];
    float4 w3b = *(const float4*)&W3[c * 2 + 4];
    float b30 = b3[0], b31 = b3[1];
#pragma unroll
    for (int i = 0; i < 8; i++) {
        float4 v;
        v.x = fmaxf(acc[i][0] + bb.x, 0.f);
        v.y = fmaxf(acc[i][1] + bb.y, 0.f);
        v.z = fmaxf(acc[i][2] + bb.z, 0.f);
        v.w = fmaxf(acc[i][3] + bb.w, 0.f);
        float p0 = v.x * w3a.x + v.y * w3a.z + v.z * w3b.x + v.w * w3b.z;
        float p1 = v.x * w3a.y + v.y * w3a.w + v.z * w3b.y + v.w * w3b.w;
#pragma unroll
        for (int o = 16; o; o >>= 1) {
            p0 += __shfl_xor_sync(0xffffffffu, p0, o);
            p1 += __shfl_xor_sync(0xffffffffu, p1, o);
        }
        int r = rowBase + warp * 8 + i;
        if (lane == 0 && r < NN) {
            out[r * 2 + 0] = p0 + b30;
            out[r * 2 + 1] = p1 + b31;
        }
    }
}

// ---------------- launch ----------------
extern "C" void kernel_launch(void* const* d_in, const int* in_sizes, int n_in,
                              void* d_out, int out_size) {
    const float* x    = (const float*)d_in[0];
    const int*   ei   = (const int*)  d_in[1];
    const float* ew   = (const float*)d_in[2];
    const float* Wl   = (const float*)d_in[3];
    const float* bl   = (const float*)d_in[4];
    const float* Wr   = (const float*)d_in[5];
    const float* br   = (const float*)d_in[6];
    const float* We   = (const float*)d_in[7];
    const float* att  = (const float*)d_in[8];
    const float* bgat = (const float*)d_in[9];
    const float* W2   = (const float*)d_in[10];
    const float* bgcn = (const float*)d_in[11];
    const float* W3   = (const float*)d_in[12];
    const float* b3   = (const float*)d_in[13];
    float* out = (float*)d_out;

    static bool attr_set = false;
    if (!attr_set) {
        cudaFuncSetAttribute(k_gemm, cudaFuncAttributeMaxDynamicSharedMemorySize,
                             (C * C + 64 * C) * (int)sizeof(float));
        attr_set = true;
    }

    const int TPB = 256;
    k_zerocnt<<<(NN + TPB - 1) / TPB, TPB>>>();
    k_hist   <<<(ET + TPB - 1) / TPB, TPB>>>(ei, out);
    k_scan   <<<1, 1024>>>();
    k_scatter<<<(ET + TPB - 1) / TPB, TPB>>>(ei, ew);
    k_lin    <<<(NN * C + TPB - 1) / TPB, TPB>>>(x, Wl, bl, Wr, br);
    k_gat    <<<(NN * 32 + TPB - 1) / TPB, TPB>>>(We, att, bgat, out);
    k_gcn    <<<(NN * 32 + TPB - 1) / TPB, TPB>>>();
    k_gemm   <<<(NN + 63) / 64, TPB, (C * C + 64 * C) * sizeof(float)>>>(W2, bgcn, W3, b3, out);
}

// round 5
// speedup vs baseline: 2.5870x; 1.0913x over previous
#include <cuda_runtime.h>
#include <cuda_fp16.h>

#define NN   100000
#define EE   1600000
#define ET   (EE + NN)     // 1,700,000
#define C    128
#define DIN  6

// ---------------- device scratch ----------------
__device__ __half g_xl[NN * C];    // fp16 feature table (gathered by k_gat)
__device__ float  g_xr[NN * C];    // fp32 (coalesced per-node read)
__device__ __half g_h [NN * C];    // fp16 feature table (gathered by k_gemm)
__device__ float  g_ex[ET];        // CSR-ordered exp(logit)
__device__ float  g_alpha[ET];     // CSR-ordered alpha
__device__ int    g_srca[ET];      // CSR-ordered src
__device__ int    g_eid[ET];       // CSR-ordered original edge id
__device__ float2 g_ef[ET];        // CSR-ordered edge features
__device__ int    g_cnt[NN];
__device__ int    g_rowptr[NN + 1];
__device__ int    g_cur[NN];

// packed f32x2 helpers (Blackwell)
#define PK2(d, lo, hi) asm("mov.b64 %0, {%1,%2};" : "=l"(d) : "f"(lo), "f"(hi))
#define FMA2(d, a, b)  asm("fma.rn.f32x2 %0, %1, %2, %0;" : "+l"(d) : "l"(a), "l"(b))
#define UNPK2(lo, hi, s) asm("mov.b64 {%0,%1}, %2;" : "=f"(lo), "=f"(hi) : "l"(s))

// load 4 fp16 channels -> float4 (8 bytes)
__device__ __forceinline__ float4 ldh4(const __half* p) {
    uint2 u = *(const uint2*)p;
    __half2 h0, h1;
    *(unsigned*)&h0 = u.x; *(unsigned*)&h1 = u.y;
    float2 f0 = __half22float2(h0), f1 = __half22float2(h1);
    return make_float4(f0.x, f0.y, f1.x, f1.y);
}

// ---------------- K0: zero histogram ----------------
__global__ void k_zerocnt() {
    int i = blockIdx.x * blockDim.x + threadIdx.x;
    if (i < NN) g_cnt[i] = 0;
}

// ---------------- K1: histogram over dst + write src/dst stack output ----------------
__global__ void k_hist(const int* __restrict__ ei, float* __restrict__ out) {
    int e = blockIdx.x * blockDim.x + threadIdx.x;
    if (e >= ET) return;
    int s, d;
    if (e < EE) { s = ei[e]; d = ei[EE + e]; }
    else        { s = e - EE; d = s; }
    atomicAdd(&g_cnt[d], 1);
    out[NN * 2 + e]      = (float)s;
    out[NN * 2 + ET + e] = (float)d;
}

// ---------------- K2: exclusive scan (single block, 1024 threads) ----------------
__global__ void k_scan() {
    __shared__ int ssum[1024];
    const int CH = (NN + 1023) / 1024;
    int t = threadIdx.x;
    int beg = t * CH; if (beg > NN) beg = NN;
    int end = beg + CH; if (end > NN) end = NN;
    int s = 0;
    for (int j = beg; j < end; j++) s += g_cnt[j];
    ssum[t] = s;
    __syncthreads();
    for (int off = 1; off < 1024; off <<= 1) {
        int v = (t >= off) ? ssum[t - off] : 0;
        __syncthreads();
        ssum[t] += v;
        __syncthreads();
    }
    int run = t ? ssum[t - 1] : 0;
    for (int j = beg; j < end; j++) {
        g_rowptr[j] = run;
        g_cur[j]    = run;
        run += g_cnt[j];
    }
    if (t == 0) g_rowptr[NN] = ET;
}

// ---------------- K3: scatter edges into CSR slots ----------------
__global__ void k_scatter(const int* __restrict__ ei, const float* __restrict__ ew) {
    int e = blockIdx.x * blockDim.x + threadIdx.x;
    if (e >= ET) return;
    int s, d; float e0 = 0.f, e1 = 0.f;
    if (e < EE) {
        s = ei[e]; d = ei[EE + e];
        float2 v = *(const float2*)&ew[2 * e];
        e0 = v.x; e1 = v.y;
    } else { s = e - EE; d = s; }
    int pos = atomicAdd(&g_cur[d], 1);
    g_srca[pos] = s;
    g_eid[pos]  = e;
    g_ef[pos]   = make_float2(e0, e1);
}

// ---------------- K4: xl = fp16(x@Wl + bl) ; xr = x@Wr + br ----------------
__global__ void k_lin(const float* __restrict__ x,
                      const float* __restrict__ Wl, const float* __restrict__ bl,
                      const float* __restrict__ Wr, const float* __restrict__ br) {
    int idx = blockIdx.x * blockDim.x + threadIdx.x;   // over NN*64 half2 pairs
    if (idx >= NN * 64) return;
    int n = idx >> 6, cp = (idx & 63) * 2;
    float a0 = bl[cp], a1 = bl[cp + 1];
    float b0 = br[cp], b1 = br[cp + 1];
#pragma unroll
    for (int k = 0; k < DIN; k++) {
        float xv = x[n * DIN + k];
        a0 += xv * Wl[k * C + cp];
        a1 += xv * Wl[k * C + cp + 1];
        b0 += xv * Wr[k * C + cp];
        b1 += xv * Wr[k * C + cp + 1];
    }
    ((__half2*)g_xl)[idx] = __floats2half2_rn(a0, a1);
    *(float2*)&g_xr[n * C + cp] = make_float2(b0, b1);
}

// per-lane partial logit for one edge (4 channels)
__device__ __forceinline__ float lane_logit(const float4 a, const float4 xr,
                                            const float2 ef,
                                            const float4 w0, const float4 w1,
                                            const float4 at) {
    float p = 0.f, m;
    m = a.x + xr.x + ef.x * w0.x + ef.y * w1.x; m = m > 0.f ? m : 0.2f * m; p += m * at.x;
    m = a.y + xr.y + ef.x * w0.y + ef.y * w1.y; m = m > 0.f ? m : 0.2f * m; p += m * at.y;
    m = a.z + xr.z + ef.x * w0.z + ef.y * w1.z; m = m > 0.f ? m : 0.2f * m; p += m * at.z;
    m = a.w + xr.w + ef.x * w0.w + ef.y * w1.w; m = m > 0.f ? m : 0.2f * m; p += m * at.w;
    return p;
}

// ---------------- K5: fused GATv2, single gather pass (fp16 xl) ----------------
__global__ void k_gat(const float* __restrict__ We, const float* __restrict__ att,
                      const float* __restrict__ bgat, float* __restrict__ out) {
    int node = (blockIdx.x * blockDim.x + threadIdx.x) >> 5;
    int lane = threadIdx.x & 31;
    if (node >= NN) return;
    int c = lane * 4;
    float4 w0 = *(const float4*)&We[c];
    float4 w1 = *(const float4*)&We[C + c];
    float4 at = *(const float4*)&att[c];
    float4 xr = *(const float4*)&g_xr[node * C + c];
    int beg = g_rowptr[node], end = g_rowptr[node + 1];

    float den = 0.f;
    float4 acc = make_float4(0.f, 0.f, 0.f, 0.f);
    int j = beg;
    for (; j + 3 < end; j += 4) {
        int s0 = g_srca[j], s1 = g_srca[j + 1], s2 = g_srca[j + 2], s3 = g_srca[j + 3];
        float2 f0 = g_ef[j], f1 = g_ef[j + 1], f2 = g_ef[j + 2], f3 = g_ef[j + 3];
        const float4 a0 = ldh4(&g_xl[s0 * C + c]);
        const float4 a1 = ldh4(&g_xl[s1 * C + c]);
        const float4 a2 = ldh4(&g_xl[s2 * C + c]);
        const float4 a3 = ldh4(&g_xl[s3 * C + c]);
        float p0 = lane_logit(a0, xr, f0, w0, w1, at);
        float p1 = lane_logit(a1, xr, f1, w0, w1, at);
        float p2 = lane_logit(a2, xr, f2, w0, w1, at);
        float p3 = lane_logit(a3, xr, f3, w0, w1, at);
#pragma unroll
        for (int o = 16; o; o >>= 1) {
            p0 += __shfl_xor_sync(0xffffffffu, p0, o);
            p1 += __shfl_xor_sync(0xffffffffu, p1, o);
            p2 += __shfl_xor_sync(0xffffffffu, p2, o);
            p3 += __shfl_xor_sync(0xffffffffu, p3, o);
        }
        float v0 = __expf(p0), v1 = __expf(p1), v2 = __expf(p2), v3 = __expf(p3);
        if (lane == 0) {
            g_ex[j] = v0; g_ex[j + 1] = v1; g_ex[j + 2] = v2; g_ex[j + 3] = v3;
        }
        den += (v0 + v1) + (v2 + v3);
        acc.x += v0 * a0.x + v1 * a1.x + v2 * a2.x + v3 * a3.x;
        acc.y += v0 * a0.y + v1 * a1.y + v2 * a2.y + v3 * a3.y;
        acc.z += v0 * a0.z + v1 * a1.z + v2 * a2.z + v3 * a3.z;
        acc.w += v0 * a0.w + v1 * a1.w + v2 * a2.w + v3 * a3.w;
    }
    for (; j < end; j++) {
        int s = g_srca[j];
        float2 f = g_ef[j];
        const float4 a = ldh4(&g_xl[s * C + c]);
        float p = lane_logit(a, xr, f, w0, w1, at);
#pragma unroll
        for (int o = 16; o; o >>= 1) p += __shfl_xor_sync(0xffffffffu, p, o);
        float v = __expf(p);
        if (lane == 0) g_ex[j] = v;
        den += v;
        acc.x += v * a.x;
        acc.y += v * a.y;
        acc.z += v * a.z;
        acc.w += v * a.w;
    }
    float inv = 1.f / den;

    // pass B: alpha write-out, lanes parallel over edges
    for (int jj = beg + lane; jj < end; jj += 32) {
        float al = g_ex[jj] * inv;
        g_alpha[jj] = al;
        out[(long long)NN * 2 + 2LL * ET + g_eid[jj]] = al;
    }

    float4 bb = *(const float4*)&bgat[c];
    float hx = fmaxf(acc.x * inv + bb.x, 0.f);
    float hy = fmaxf(acc.y * inv + bb.y, 0.f);
    float hz = fmaxf(acc.z * inv + bb.z, 0.f);
    float hw = fmaxf(acc.w * inv + bb.w, 0.f);
    uint2 hu;
    *(__half2*)&hu.x = __floats2half2_rn(hx, hy);
    *(__half2*)&hu.y = __floats2half2_rn(hz, hw);
    *(uint2*)&g_h[node * C + c] = hu;
}

// ---------------- K6: fused GCN gather + GEMM + head ----------------
// block = 256 threads, 64 nodes. Gather t rows into smem, then
// out = relu(t@W2 + b_gcn) @ W3 + b3 using f32x2 packed FMA.
__global__ void k_gemm(const float* __restrict__ W2, const float* __restrict__ bg,
                       const float* __restrict__ W3, const float* __restrict__ b3,
                       float* __restrict__ out) {
    __shared__ float ts[64 * C];
    int lane = threadIdx.x & 31, warp = threadIdx.x >> 5;
    int rowBase = blockIdx.x * 64;
    int c = lane * 4;

    // gather phase: t[node] = sum alpha * h[src]  (deg==1 => norm==alpha)
#pragma unroll
    for (int i = 0; i < 8; i++) {
        int node = rowBase + warp * 8 + i;
        float4 acc0 = make_float4(0.f, 0.f, 0.f, 0.f);
        float4 acc1 = make_float4(0.f, 0.f, 0.f, 0.f);
        if (node < NN) {
            int beg = g_rowptr[node], end = g_rowptr[node + 1];
            int j = beg;
            for (; j + 1 < end; j += 2) {
                int s0 = g_srca[j], s1 = g_srca[j + 1];
                float al0 = g_alpha[j], al1 = g_alpha[j + 1];
                const float4 h0 = ldh4(&g_h[s0 * C + c]);
                const float4 h1 = ldh4(&g_h[s1 * C + c]);
                acc0.x += al0 * h0.x; acc1.x += al1 * h1.x;
                acc0.y += al0 * h0.y; acc1.y += al1 * h1.y;
                acc0.z += al0 * h0.z; acc1.z += al1 * h1.z;
                acc0.w += al0 * h0.w; acc1.w += al1 * h1.w;
            }
            if (j < end) {
                int s = g_srca[j];
                float al = g_alpha[j];
                const float4 hv = ldh4(&g_h[s * C + c]);
                acc0.x += al * hv.x;
                acc0.y += al * hv.y;
                acc0.z += al * hv.z;
                acc0.w += al * hv.w;
            }
            acc0.x += acc1.x; acc0.y += acc1.y; acc0.z += acc1.z; acc0.w += acc1.w;
        }
        *(float4*)&ts[(warp * 8 + i) * C + c] = acc0;
    }
    __syncthreads();

    // GEMM phase: acc[row][col] over 128 k, f32x2 packed (col pairs)
    unsigned long long acc2[8][2];
#pragma unroll
    for (int i = 0; i < 8; i++) { acc2[i][0] = 0ull; acc2[i][1] = 0ull; }

    for (int k4 = 0; k4 < C; k4 += 4) {
        unsigned long long wa[4], wb[4];
#pragma unroll
        for (int kk = 0; kk < 4; kk++) {
            float4 wv = __ldg((const float4*)&W2[(k4 + kk) * C + c]);
            PK2(wa[kk], wv.x, wv.y);
            PK2(wb[kk], wv.z, wv.w);
        }
#pragma unroll
        for (int i = 0; i < 8; i++) {
            float4 tv = *(const float4*)&ts[(warp * 8 + i) * C + k4];
            unsigned long long t0, t1, t2, t3;
            PK2(t0, tv.x, tv.x);
            PK2(t1, tv.y, tv.y);
            PK2(t2, tv.z, tv.z);
            PK2(t3, tv.w, tv.w);
            FMA2(acc2[i][0], t0, wa[0]); FMA2(acc2[i][1], t0, wb[0]);
            FMA2(acc2[i][0], t1, wa[1]); FMA2(acc2[i][1], t1, wb[1]);
            FMA2(acc2[i][0], t2, wa[2]); FMA2(acc2[i][1], t2, wb[2]);
            FMA2(acc2[i][0], t3, wa[3]); FMA2(acc2[i][1], t3, wb[3]);
        }
    }

    float4 bb  = *(const float4*)&bg[c];
    float4 w3a = *(const float4*)&W3[c * 2];
    float4 w3b = *(const float4*)&W3[c * 2 + 4];
    float b30 = b3[0], b31 = b3[1];
#pragma unroll
    for (int i = 0; i < 8; i++) {
        float a0, a1, a2, a3;
        UNPK2(a0, a1, acc2[i][0]);
        UNPK2(a2, a3, acc2[i][1]);
        float vx = fmaxf(a0 + bb.x, 0.f);
        float vy = fmaxf(a1 + bb.y, 0.f);
        float vz = fmaxf(a2 + bb.z, 0.f);
        float vw = fmaxf(a3 + bb.w, 0.f);
        float p0 = vx * w3a.x + vy * w3a.z + vz * w3b.x + vw * w3b.z;
        float p1 = vx * w3a.y + vy * w3a.w + vz * w3b.y + vw * w3b.w;
#pragma unroll
        for (int o = 16; o; o >>= 1) {
            p0 += __shfl_xor_sync(0xffffffffu, p0, o);
            p1 += __shfl_xor_sync(0xffffffffu, p1, o);
        }
        int r = rowBase + warp * 8 + i;
        if (lane == 0 && r < NN) {
            out[r * 2 + 0] = p0 + b30;
            out[r * 2 + 1] = p1 + b31;
        }
    }
}

// ---------------- launch ----------------
extern "C" void kernel_launch(void* const* d_in, const int* in_sizes, int n_in,
                              void* d_out, int out_size) {
    const float* x    = (const float*)d_in[0];
    const int*   ei   = (const int*)  d_in[1];
    const float* ew   = (const float*)d_in[2];
    const float* Wl   = (const float*)d_in[3];
    const float* bl   = (const float*)d_in[4];
    const float* Wr   = (const float*)d_in[5];
    const float* br   = (const float*)d_in[6];
    const float* We   = (const float*)d_in[7];
    const float* att  = (const float*)d_in[8];
    const float* bgat = (const float*)d_in[9];
    const float* W2   = (const float*)d_in[10];
    const float* bgcn = (const float*)d_in[11];
    const float* W3   = (const float*)d_in[12];
    const float* b3   = (const float*)d_in[13];
    float* out = (float*)d_out;

    const int TPB = 256;
    k_zerocnt<<<(NN + TPB - 1) / TPB, TPB>>>();
    k_hist   <<<(ET + TPB - 1) / TPB, TPB>>>(ei, out);
    k_scan   <<<1, 1024>>>();
    k_scatter<<<(ET + TPB - 1) / TPB, TPB>>>(ei, ew);
    k_lin    <<<(NN * 64 + TPB - 1) / TPB, TPB>>>(x, Wl, bl, Wr, br);
    k_gat    <<<(NN * 32 + TPB - 1) / TPB, TPB>>>(We, att, bgat, out);
    k_gemm   <<<(NN + 63) / 64, TPB>>>(W2, bgcn, W3, b3, out);
}